// round 12
// baseline (speedup 1.0000x reference)
#include <cuda_runtime.h>
#include <cuda_bf16.h>
#include <mma.h>
using namespace nvcuda;

#define ND 128
#define HD 256
#define LVLS 4
#define PTPB 512          // prep threads
#define LTPB 256          // level threads (8 warps)
#define NPB 64            // nodes per block tile (2 CTAs/SM)
#define AST 136           // bf16 smem row stride (pad: 272B, 16B-multiple)
#define CST 132           // fp32 C smem row stride
#define TOTAL_NODES 52400

__device__ __nv_bfloat16 g_Mh[LVLS][ND * ND];  // hi part of M = Wv@Wo, row-major [k][j]
__device__ __nv_bfloat16 g_Ml[LVLS][ND * ND];  // lo part
__device__ float g_c[LVLS][ND];                // c = bv@Wo (fp32)
__device__ unsigned char g_mask[TOTAL_NODES];

__device__ __forceinline__ int sel4(int4 v, int l) {
    return l == 0 ? v.x : l == 1 ? v.y : l == 2 ? v.z : v.w;
}

// Prep: M = Wv@Wo -> bf16 hi/lo, c = bv@Wo, + edge-target mask scatter
// (hidden under the latency-bound Wo stream). Mask pre-zeroed by memset node.
__global__ __launch_bounds__(PTPB)
void prep_all_k(const float* __restrict__ Wv, const float* __restrict__ Wo,
                const float* __restrict__ bv,
                __nv_bfloat16* __restrict__ Mh, __nv_bfloat16* __restrict__ Mlo,
                float* __restrict__ cv,
                const int* __restrict__ t0, const int* __restrict__ t1,
                const int* __restrict__ t2, const int* __restrict__ t3,
                int4 ecum4, int4 noff, unsigned char* __restrict__ mask) {
    __shared__ float wv_s[2 * HD];
    __shared__ float bv_s[HD];
    __shared__ float part[9 * ND];

    const int tid = threadIdx.x;
    const int lvl = blockIdx.x >> 6, rg = blockIdx.x & 63;
    const int k0 = rg * 2;
    const float* Wvl = Wv + (size_t)lvl * ND * HD;
    const float* Wol = Wo + (size_t)lvl * HD * ND;
    const int j = tid & 127, th = tid >> 7;

    // mark scatter: 1 quarter-edge (int4) per thread, fire-and-forget
    {
        int i = blockIdx.x * PTPB + tid;
        if (i < ecum4.w) {
            const int* t; int off, no;
            if (i < ecum4.x)      { t = t0; off = 0;       no = noff.x; }
            else if (i < ecum4.y) { t = t1; off = ecum4.x; no = noff.y; }
            else if (i < ecum4.z) { t = t2; off = ecum4.y; no = noff.z; }
            else                  { t = t3; off = ecum4.z; no = noff.w; }
            int4 v = reinterpret_cast<const int4*>(t)[i - off];
            unsigned char* mb = mask + no;
            mb[v.x] = 1; mb[v.y] = 1; mb[v.z] = 1; mb[v.w] = 1;
        }
    }

    if (tid < 2 * HD) wv_s[tid] = Wvl[k0 * HD + tid];
    if (tid < HD) bv_s[tid] = bv[lvl * HD + tid];
    __syncthreads();

    const int tBase = th * (HD / 4);
    float acc0 = 0.f, acc1 = 0.f, accc = 0.f;
    #pragma unroll
    for (int tt = 0; tt < HD / 4; tt += 16) {
        float wo[16];
        #pragma unroll
        for (int u = 0; u < 16; u++)
            wo[u] = Wol[(tBase + tt + u) * ND + j];
        #pragma unroll
        for (int u = 0; u < 16; u++) {
            int t = tBase + tt + u;
            acc0 += wv_s[t] * wo[u];
            acc1 += wv_s[HD + t] * wo[u];
            accc += bv_s[t] * wo[u];
        }
    }

    if (th > 0) {
        float* p = part + (th - 1) * 3 * ND;
        p[0 * ND + j] = acc0;
        p[1 * ND + j] = acc1;
        p[2 * ND + j] = accc;
    }
    __syncthreads();
    if (th == 0) {
        #pragma unroll
        for (int q = 0; q < 3; q++) {
            const float* p = part + q * 3 * ND;
            acc0 += p[0 * ND + j];
            acc1 += p[1 * ND + j];
            accc += p[2 * ND + j];
        }
        __nv_bfloat16* Mhl = Mh + (size_t)lvl * ND * ND;
        __nv_bfloat16* Mll = Mlo + (size_t)lvl * ND * ND;
        float v0 = acc0, v1 = acc1;
        __nv_bfloat16 h0 = __float2bfloat16(v0);
        __nv_bfloat16 h1 = __float2bfloat16(v1);
        Mhl[(k0 + 0) * ND + j] = h0;
        Mhl[(k0 + 1) * ND + j] = h1;
        Mll[(k0 + 0) * ND + j] = __float2bfloat16(v0 - __bfloat162float(h0));
        Mll[(k0 + 1) * ND + j] = __float2bfloat16(v1 - __bfloat162float(h1));
        if (rg == 0) cv[lvl * ND + j] = accc;
    }
}

// Tensor-core level kernel: 64-node tile, 8 warps (16x64 warp tile), 2 CTAs/SM.
// bf16 hi/lo split GEMM (3 passes) + mask/residual/LN.
__global__ __launch_bounds__(LTPB, 2)
void level_all_k(const float* __restrict__ n0i, const float* __restrict__ n1i,
                 const float* __restrict__ n2i, const float* __restrict__ n3i,
                 const unsigned char* __restrict__ mask,
                 const __nv_bfloat16* __restrict__ Mhb,
                 const __nv_bfloat16* __restrict__ Mlb,
                 const float* __restrict__ cvb, const float* __restrict__ bob,
                 const float* __restrict__ gb, const float* __restrict__ bb,
                 float* __restrict__ out, int4 bstart, int4 noff, int4 ncnt) {
    extern __shared__ char smraw[];
    __nv_bfloat16* Ah   = reinterpret_cast<__nv_bfloat16*>(smraw);   // NPB*AST
    __nv_bfloat16* Al   = Ah + NPB * AST;
    __nv_bfloat16* Mh_s = Al + NPB * AST;                            // ND*AST
    __nv_bfloat16* Ml_s = Mh_s + ND * AST;
    float* C_s = reinterpret_cast<float*>(Mh_s);   // overlay after mainloop (33.8KB<=34.8KB)
    float* bo_s = reinterpret_cast<float*>(Ml_s + ND * AST);
    float* cv_s = bo_s + ND;
    float* g_s  = cv_s + ND;
    float* b_s  = g_s + ND;
    float* mk_s = b_s + ND;       // NPB
    float* mu_s = mk_s + NPB;     // NPB
    float* rs_s = mu_s + NPB;     // NPB

    const int tid = threadIdx.x;
    const int b = blockIdx.x;

    int lvl, b0;
    if (b < bstart.x)      { lvl = 0; b0 = 0; }
    else if (b < bstart.y) { lvl = 1; b0 = bstart.x; }
    else if (b < bstart.z) { lvl = 2; b0 = bstart.y; }
    else                   { lvl = 3; b0 = bstart.z; }

    const float* nodes = lvl == 0 ? n0i : lvl == 1 ? n1i : lvl == 2 ? n2i : n3i;
    const int N  = sel4(ncnt, lvl);
    const int nO = sel4(noff, lvl);
    float* outl = out + (size_t)nO * ND;
    const int nodeBase = (b - b0) * NPB;

    // Stage params + mask
    if (tid < ND) {
        bo_s[tid] = bob[lvl * ND + tid];
        cv_s[tid] = cvb[lvl * ND + tid];
        g_s[tid]  = gb[lvl * ND + tid];
        b_s[tid]  = bb[lvl * ND + tid];
    } else if (tid < ND + NPB) {
        int row = tid - ND;
        int gn = nodeBase + row;
        mk_s[row] = (gn < N && mask[nO + gn]) ? 1.f : 0.f;
    }

    // Stage M bf16 hi/lo into padded smem (uint4 = 8 bf16 per copy)
    {
        const uint4* mh4 = reinterpret_cast<const uint4*>(Mhb + (size_t)lvl * ND * ND);
        const uint4* ml4 = reinterpret_cast<const uint4*>(Mlb + (size_t)lvl * ND * ND);
        #pragma unroll
        for (int r = 0; r < 8; r++) {
            int idx = tid + r * LTPB;         // 0..2047 (128 rows x 16 chunks)
            int row = idx >> 4, c8 = idx & 15;
            *reinterpret_cast<uint4*>(Mh_s + row * AST + c8 * 8) = mh4[idx];
            *reinterpret_cast<uint4*>(Ml_s + row * AST + c8 * 8) = ml4[idx];
        }
    }

    // Stage A: fp32 coalesced load -> bf16 hi/lo split (64 rows x 32 float4)
    {
        const float4* nodes4 = reinterpret_cast<const float4*>(nodes);
        #pragma unroll
        for (int r = 0; r < 8; r++) {
            int idx = tid + r * LTPB;         // 0..2047
            int node = idx >> 5, q = idx & 31;
            int gn = nodeBase + node;
            float4 v = (gn < N) ? nodes4[gn * 32 + q]
                                : make_float4(0.f, 0.f, 0.f, 0.f);
            __nv_bfloat16 hx = __float2bfloat16(v.x);
            __nv_bfloat16 hy = __float2bfloat16(v.y);
            __nv_bfloat16 hz = __float2bfloat16(v.z);
            __nv_bfloat16 hw = __float2bfloat16(v.w);
            __nv_bfloat162 hA; hA.x = hx; hA.y = hy;
            __nv_bfloat162 hB; hB.x = hz; hB.y = hw;
            __nv_bfloat162 lA = __floats2bfloat162_rn(v.x - __bfloat162float(hx),
                                                      v.y - __bfloat162float(hy));
            __nv_bfloat162 lB = __floats2bfloat162_rn(v.z - __bfloat162float(hz),
                                                      v.w - __bfloat162float(hw));
            int off = node * AST + q * 4;
            *reinterpret_cast<__nv_bfloat162*>(Ah + off)     = hA;
            *reinterpret_cast<__nv_bfloat162*>(Ah + off + 2) = hB;
            *reinterpret_cast<__nv_bfloat162*>(Al + off)     = lA;
            *reinterpret_cast<__nv_bfloat162*>(Al + off + 2) = lB;
        }
    }
    __syncthreads();

    // Mainloop: 8 warps, warp tile 16 nodes x 64 cols, 3 split-precision passes.
    const int wid = tid >> 5;
    const int wr = wid >> 1, wc = wid & 1;   // wr 0..3 (16-row band), wc 0..1 (64-col half)
    wmma::fragment<wmma::accumulator, 16, 16, 16, float> acc[4];
    #pragma unroll
    for (int j = 0; j < 4; j++) wmma::fill_fragment(acc[j], 0.f);

    #pragma unroll
    for (int p = 0; p < 3; p++) {
        const __nv_bfloat16* Ap = (p == 1) ? Al : Ah;
        const __nv_bfloat16* Mp = (p == 2) ? Ml_s : Mh_s;
        #pragma unroll
        for (int k = 0; k < ND; k += 16) {
            wmma::fragment<wmma::matrix_a, 16, 16, 16, __nv_bfloat16, wmma::row_major> af;
            wmma::load_matrix_sync(af, Ap + (wr * 16) * AST + k, AST);
            #pragma unroll
            for (int j = 0; j < 4; j++) {
                wmma::fragment<wmma::matrix_b, 16, 16, 16, __nv_bfloat16, wmma::row_major> bf;
                wmma::load_matrix_sync(bf, Mp + k * AST + wc * 64 + j * 16, AST);
                wmma::mma_sync(acc[j], af, bf, acc[j]);
            }
        }
    }
    __syncthreads();   // all M reads complete before overwriting region as C_s

    #pragma unroll
    for (int j = 0; j < 4; j++)
        wmma::store_matrix_sync(C_s + (wr * 16) * CST + wc * 64 + j * 16,
                                acc[j], CST, wmma::mem_row_major);
    __syncthreads();

    // LN stats: 4 threads per row (32 cols each), 2-step shfl combine
    {
        int row = tid >> 2, quad = tid & 3;   // 64 rows x 4
        float mk = mk_s[row];
        float s = 0.f, s2 = 0.f;
        int cb = quad * 32;
        #pragma unroll 8
        for (int c = 0; c < 32; c++) {
            int col = cb + c;
            float xr = __bfloat162float(Ah[row * AST + col]) +
                       __bfloat162float(Al[row * AST + col]);
            float x = xr + bo_s[col] + mk * (C_s[row * CST + col] + cv_s[col]);
            s += x; s2 += x * x;
        }
        s  += __shfl_xor_sync(0xffffffffu, s, 1);
        s2 += __shfl_xor_sync(0xffffffffu, s2, 1);
        s  += __shfl_xor_sync(0xffffffffu, s, 2);
        s2 += __shfl_xor_sync(0xffffffffu, s2, 2);
        if (quad == 0) {
            float mu = s * (1.f / 128.f);
            mu_s[row] = mu;
            rs_s[row] = rsqrtf(s2 * (1.f / 128.f) - mu * mu + 1e-5f);
        }
    }
    __syncthreads();

    // Normalize + affine, coalesced float4 stores (64 rows x 32 float4)
    #pragma unroll
    for (int r = 0; r < 8; r++) {
        int idx = tid + r * LTPB;             // 0..2047 float4s
        int row = idx >> 5, q = idx & 31;
        int gn = nodeBase + row;
        if (gn < N) {
            float mk = mk_s[row], mu = mu_s[row], rs = rs_s[row];
            float4 o;
            float* op = &o.x;
            #pragma unroll
            for (int e = 0; e < 4; e++) {
                int col = q * 4 + e;
                float xr = __bfloat162float(Ah[row * AST + col]) +
                           __bfloat162float(Al[row * AST + col]);
                float x = xr + bo_s[col] + mk * (C_s[row * CST + col] + cv_s[col]);
                op[e] = (x - mu) * rs * g_s[col] + b_s[col];
            }
            *reinterpret_cast<float4*>(outl + (size_t)gn * ND + q * 4) = o;
        }
    }
}

static const int SMEM_BYTES = (2 * NPB + 2 * ND) * AST * 2      // bf16 tiles
                            + (4 * ND + 3 * NPB) * (int)sizeof(float);  // params

extern "C" void kernel_launch(void* const* d_in, const int* in_sizes, int n_in,
                              void* d_out, int out_size) {
    (void)n_in; (void)out_size;
    int NN[LVLS], NE[LVLS], noffA[LVLS];
    int cumN = 0;
    for (int i = 0; i < LVLS; i++) {
        NN[i] = in_sizes[i * 3] / ND;
        NE[i] = in_sizes[i * 3 + 2] / 2;
        noffA[i] = cumN;
        cumN += NN[i];
    }
    int ec4[LVLS]; int cumE4 = 0;
    for (int i = 0; i < LVLS; i++) { cumE4 += NE[i] / 4; ec4[i] = cumE4; }

    const float* Wv    = (const float*)d_in[16];
    const float* bv    = (const float*)d_in[17];
    const float* Wo    = (const float*)d_in[20];
    const float* bo    = (const float*)d_in[21];
    const float* gamma = (const float*)d_in[22];
    const float* beta  = (const float*)d_in[23];
    float* out = (float*)d_out;

    unsigned char* maskp = nullptr;
    __nv_bfloat16* Mhp = nullptr;
    __nv_bfloat16* Mlp = nullptr;
    float* cp = nullptr;
    cudaGetSymbolAddress((void**)&maskp, g_mask);
    cudaGetSymbolAddress((void**)&Mhp, g_Mh);
    cudaGetSymbolAddress((void**)&Mlp, g_Ml);
    cudaGetSymbolAddress((void**)&cp, g_c);

    cudaFuncSetAttribute(level_all_k, cudaFuncAttributeMaxDynamicSharedMemorySize, SMEM_BYTES);

    // 1) zero mask
    cudaMemsetAsync(maskp, 0, cumN);

    // 2) prep: M hi/lo bf16 + c + mask marking
    const int* t0 = (const int*)d_in[2]  + NE[0];
    const int* t1 = (const int*)d_in[5]  + NE[1];
    const int* t2 = (const int*)d_in[8]  + NE[2];
    const int* t3 = (const int*)d_in[11] + NE[3];
    int4 ecum4 = make_int4(ec4[0], ec4[1], ec4[2], ec4[3]);
    int4 noff = make_int4(noffA[0], noffA[1], noffA[2], noffA[3]);
    prep_all_k<<<LVLS * 64, PTPB>>>(Wv, Wo, bv, Mhp, Mlp, cp,
                                    t0, t1, t2, t3, ecum4, noff, maskp);

    // 3) tensor-core level kernel (64-node tiles, 2 CTAs/SM)
    int bs[LVLS], cumB = 0;
    for (int i = 0; i < LVLS; i++) { cumB += (NN[i] + NPB - 1) / NPB; bs[i] = cumB; }
    int4 bstart = make_int4(bs[0], bs[1], bs[2], bs[3]);
    int4 ncnt = make_int4(NN[0], NN[1], NN[2], NN[3]);
    level_all_k<<<cumB, LTPB, SMEM_BYTES>>>(
        (const float*)d_in[0], (const float*)d_in[3],
        (const float*)d_in[6], (const float*)d_in[9],
        maskp, Mhp, Mlp, cp, bo, gamma, beta, out, bstart, noff, ncnt);
}

// round 15
// speedup vs baseline: 1.0510x; 1.0510x over previous
#include <cuda_runtime.h>
#include <cuda_bf16.h>
#include <cstdint>
#include <mma.h>
using namespace nvcuda;

#define ND 128
#define HD 256
#define LVLS 4
#define PTPB 512
#define LTPB 256          // 8 warps
#define NPB 128
#define AST 136           // bf16 smem row stride
#define CST 132           // fp32 C smem row stride
#define TOTAL_NODES 52400

__device__ __nv_bfloat16 g_Mh[LVLS][ND * ND];  // hi part of M = Wv@Wo, row-major [k][j]
__device__ __nv_bfloat16 g_Ml[LVLS][ND * ND];  // lo part
__device__ float g_c[LVLS][ND];
__device__ unsigned char g_mask[TOTAL_NODES];

__device__ __forceinline__ int sel4(int4 v, int l) {
    return l == 0 ? v.x : l == 1 ? v.y : l == 2 ? v.z : v.w;
}

// Prep: M = Wv@Wo -> bf16 hi/lo (row-major), c = bv@Wo, + mask scatter hidden
// under the Wo stream. Mask pre-zeroed by memset node.
__global__ __launch_bounds__(PTPB)
void prep_all_k(const float* __restrict__ Wv, const float* __restrict__ Wo,
                const float* __restrict__ bv,
                __nv_bfloat16* __restrict__ Mh, __nv_bfloat16* __restrict__ Mlo,
                float* __restrict__ cv,
                const int* __restrict__ t0, const int* __restrict__ t1,
                const int* __restrict__ t2, const int* __restrict__ t3,
                int4 ecum4, int4 noff, unsigned char* __restrict__ mask) {
    __shared__ float wv_s[2 * HD];
    __shared__ float bv_s[HD];
    __shared__ float part[9 * ND];

    const int tid = threadIdx.x;
    const int lvl = blockIdx.x >> 6, rg = blockIdx.x & 63;
    const int k0 = rg * 2;
    const float* Wvl = Wv + (size_t)lvl * ND * HD;
    const float* Wol = Wo + (size_t)lvl * HD * ND;
    const int j = tid & 127, th = tid >> 7;

    {
        int i = blockIdx.x * PTPB + tid;
        if (i < ecum4.w) {
            const int* t; int off, no;
            if (i < ecum4.x)      { t = t0; off = 0;       no = noff.x; }
            else if (i < ecum4.y) { t = t1; off = ecum4.x; no = noff.y; }
            else if (i < ecum4.z) { t = t2; off = ecum4.y; no = noff.z; }
            else                  { t = t3; off = ecum4.z; no = noff.w; }
            int4 v = reinterpret_cast<const int4*>(t)[i - off];
            unsigned char* mb = mask + no;
            mb[v.x] = 1; mb[v.y] = 1; mb[v.z] = 1; mb[v.w] = 1;
        }
    }

    if (tid < 2 * HD) wv_s[tid] = Wvl[k0 * HD + tid];
    if (tid < HD) bv_s[tid] = bv[lvl * HD + tid];
    __syncthreads();

    const int tBase = th * (HD / 4);
    float acc0 = 0.f, acc1 = 0.f, accc = 0.f;
    #pragma unroll
    for (int tt = 0; tt < HD / 4; tt += 16) {
        float wo[16];
        #pragma unroll
        for (int u = 0; u < 16; u++)
            wo[u] = Wol[(tBase + tt + u) * ND + j];
        #pragma unroll
        for (int u = 0; u < 16; u++) {
            int t = tBase + tt + u;
            acc0 += wv_s[t] * wo[u];
            acc1 += wv_s[HD + t] * wo[u];
            accc += bv_s[t] * wo[u];
        }
    }

    if (th > 0) {
        float* p = part + (th - 1) * 3 * ND;
        p[0 * ND + j] = acc0;
        p[1 * ND + j] = acc1;
        p[2 * ND + j] = accc;
    }
    __syncthreads();
    if (th == 0) {
        #pragma unroll
        for (int q = 0; q < 3; q++) {
            const float* p = part + q * 3 * ND;
            acc0 += p[0 * ND + j];
            acc1 += p[1 * ND + j];
            accc += p[2 * ND + j];
        }
        __nv_bfloat16* Mhl = Mh + (size_t)lvl * ND * ND;
        __nv_bfloat16* Mll = Mlo + (size_t)lvl * ND * ND;
        float v0 = acc0, v1 = acc1;
        __nv_bfloat16 h0 = __float2bfloat16(v0);
        __nv_bfloat16 h1 = __float2bfloat16(v1);
        Mhl[(k0 + 0) * ND + j] = h0;
        Mhl[(k0 + 1) * ND + j] = h1;
        Mll[(k0 + 0) * ND + j] = __float2bfloat16(v0 - __bfloat162float(h0));
        Mll[(k0 + 1) * ND + j] = __float2bfloat16(v1 - __bfloat162float(h1));
        if (rg == 0) cv[lvl * ND + j] = accc;
    }
}

// wmma level kernel, 2 CTAs/SM: single resident M tile (restaged Mh->Ml),
// 3-pass bf16 hi/lo GEMM, two-phase epilogue (C in dead M region).
__global__ __launch_bounds__(LTPB, 2)
void level_all_k(const float* __restrict__ n0i, const float* __restrict__ n1i,
                 const float* __restrict__ n2i, const float* __restrict__ n3i,
                 const unsigned char* __restrict__ mask,
                 const __nv_bfloat16* __restrict__ Mhb,
                 const __nv_bfloat16* __restrict__ Mlb,
                 const float* __restrict__ cvb, const float* __restrict__ bob,
                 const float* __restrict__ gb, const float* __restrict__ bb,
                 float* __restrict__ out, int4 bstart, int4 noff, int4 ncnt) {
    extern __shared__ char smraw[];
    __nv_bfloat16* Ah = reinterpret_cast<__nv_bfloat16*>(smraw);  // NPB*AST
    __nv_bfloat16* Al = Ah + NPB * AST;
    __nv_bfloat16* Mx = Al + NPB * AST;                           // ND*AST (Mh then Ml)
    float* C_s  = reinterpret_cast<float*>(smraw + 2 * NPB * AST * 2);  // overlays Mx; 64*CST
    float* bo_s = reinterpret_cast<float*>(smraw + (2 * NPB + ND) * AST * 2);
    float* cv_s = bo_s + ND;
    float* g_s  = cv_s + ND;
    float* b_s  = g_s + ND;
    float* mk_s = b_s + ND;       // NPB

    const int tid = threadIdx.x;
    const int b = blockIdx.x;

    int lvl, b0;
    if (b < bstart.x)      { lvl = 0; b0 = 0; }
    else if (b < bstart.y) { lvl = 1; b0 = bstart.x; }
    else if (b < bstart.z) { lvl = 2; b0 = bstart.y; }
    else                   { lvl = 3; b0 = bstart.z; }

    const float* nodes = lvl == 0 ? n0i : lvl == 1 ? n1i : lvl == 2 ? n2i : n3i;
    const int N  = sel4(ncnt, lvl);
    const int nO = sel4(noff, lvl);
    float* outl = out + (size_t)nO * ND;
    const int nodeBase = (b - b0) * NPB;

    // params + mask (tid < 128 does both)
    if (tid < ND) {
        bo_s[tid] = bob[lvl * ND + tid];
        cv_s[tid] = cvb[lvl * ND + tid];
        g_s[tid]  = gb[lvl * ND + tid];
        b_s[tid]  = bb[lvl * ND + tid];
        int gn = nodeBase + tid;
        mk_s[tid] = (gn < N && mask[nO + gn]) ? 1.f : 0.f;
    }

    // Stage Mh into Mx (uint4 = 8 bf16)
    {
        const uint4* mh4 = reinterpret_cast<const uint4*>(Mhb + (size_t)lvl * ND * ND);
        #pragma unroll
        for (int r = 0; r < 8; r++) {
            int idx = tid + r * LTPB;     // 0..2047 (128 rows x 16 chunks)
            int row = idx >> 4, c8 = idx & 15;
            *reinterpret_cast<uint4*>(Mx + row * AST + c8 * 8) = mh4[idx];
        }
    }

    // Stage A: fp32 coalesced -> bf16 hi/lo
    {
        const float4* nodes4 = reinterpret_cast<const float4*>(nodes);
        #pragma unroll
        for (int r = 0; r < 16; r++) {
            int idx = tid + r * LTPB;     // 0..4095 (128 rows x 32 float4)
            int node = idx >> 5, q = idx & 31;
            int gn = nodeBase + node;
            float4 v = (gn < N) ? nodes4[(size_t)gn * 32 + q]
                                : make_float4(0.f, 0.f, 0.f, 0.f);
            __nv_bfloat16 hx = __float2bfloat16(v.x);
            __nv_bfloat16 hy = __float2bfloat16(v.y);
            __nv_bfloat16 hz = __float2bfloat16(v.z);
            __nv_bfloat16 hw = __float2bfloat16(v.w);
            __nv_bfloat162 hA; hA.x = hx; hA.y = hy;
            __nv_bfloat162 hB; hB.x = hz; hB.y = hw;
            __nv_bfloat162 lA = __floats2bfloat162_rn(v.x - __bfloat162float(hx),
                                                      v.y - __bfloat162float(hy));
            __nv_bfloat162 lB = __floats2bfloat162_rn(v.z - __bfloat162float(hz),
                                                      v.w - __bfloat162float(hw));
            int off = node * AST + q * 4;
            *reinterpret_cast<__nv_bfloat162*>(Ah + off)     = hA;
            *reinterpret_cast<__nv_bfloat162*>(Ah + off + 2) = hB;
            *reinterpret_cast<__nv_bfloat162*>(Al + off)     = lA;
            *reinterpret_cast<__nv_bfloat162*>(Al + off + 2) = lB;
        }
    }
    __syncthreads();

    // Mainloop: 8 warps, warp tile 32 nodes x 64 cols.
    const int wid = tid >> 5;
    const int wr = wid >> 1, wc = wid & 1;
    wmma::fragment<wmma::accumulator, 16, 16, 16, float> acc[2][4];
    #pragma unroll
    for (int i = 0; i < 2; i++)
        #pragma unroll
        for (int j = 0; j < 4; j++) wmma::fill_fragment(acc[i][j], 0.f);

    // passes 0,1: Ah*Mh, Al*Mh
    #pragma unroll
    for (int p = 0; p < 2; p++) {
        const __nv_bfloat16* Ap = p ? Al : Ah;
        #pragma unroll
        for (int k = 0; k < ND; k += 16) {
            wmma::fragment<wmma::matrix_a, 16, 16, 16, __nv_bfloat16, wmma::row_major> af[2];
            wmma::load_matrix_sync(af[0], Ap + (wr * 32) * AST + k, AST);
            wmma::load_matrix_sync(af[1], Ap + (wr * 32 + 16) * AST + k, AST);
            #pragma unroll
            for (int j = 0; j < 4; j++) {
                wmma::fragment<wmma::matrix_b, 16, 16, 16, __nv_bfloat16, wmma::row_major> bf;
                wmma::load_matrix_sync(bf, Mx + k * AST + wc * 64 + j * 16, AST);
                wmma::mma_sync(acc[0][j], af[0], bf, acc[0][j]);
                wmma::mma_sync(acc[1][j], af[1], bf, acc[1][j]);
            }
        }
    }
    __syncthreads();
    // restage Mx <- Ml
    {
        const uint4* ml4 = reinterpret_cast<const uint4*>(Mlb + (size_t)lvl * ND * ND);
        #pragma unroll
        for (int r = 0; r < 8; r++) {
            int idx = tid + r * LTPB;
            int row = idx >> 4, c8 = idx & 15;
            *reinterpret_cast<uint4*>(Mx + row * AST + c8 * 8) = ml4[idx];
        }
    }
    __syncthreads();
    // pass 2: Ah*Ml
    #pragma unroll
    for (int k = 0; k < ND; k += 16) {
        wmma::fragment<wmma::matrix_a, 16, 16, 16, __nv_bfloat16, wmma::row_major> af[2];
        wmma::load_matrix_sync(af[0], Ah + (wr * 32) * AST + k, AST);
        wmma::load_matrix_sync(af[1], Ah + (wr * 32 + 16) * AST + k, AST);
        #pragma unroll
        for (int j = 0; j < 4; j++) {
            wmma::fragment<wmma::matrix_b, 16, 16, 16, __nv_bfloat16, wmma::row_major> bf;
            wmma::load_matrix_sync(bf, Mx + k * AST + wc * 64 + j * 16, AST);
            wmma::mma_sync(acc[0][j], af[0], bf, acc[0][j]);
            wmma::mma_sync(acc[1][j], af[1], bf, acc[1][j]);
        }
    }
    __syncthreads();   // all Mx reads done before C_s overlays it

    // Two half-epilogues: rows [h*64, h*64+64)
    #pragma unroll
    for (int h = 0; h < 2; h++) {
        if ((wid >> 2) == h) {
            #pragma unroll
            for (int i = 0; i < 2; i++)
                #pragma unroll
                for (int j = 0; j < 4; j++)
                    wmma::store_matrix_sync(
                        C_s + (wr * 32 + i * 16 - h * 64) * CST + wc * 64 + j * 16,
                        acc[i][j], CST, wmma::mem_row_major);
        }
        __syncthreads();

        {
            const int row_l = tid >> 2, quad = tid & 3;
            const int row = h * 64 + row_l;
            const int gn = nodeBase + row;
            float s = 0.f, s2 = 0.f;
            float xv[32];
            if (gn < N) {
                float mk = mk_s[row];
                #pragma unroll
                for (int j = 0; j < 8; j++) {
                    int cb = (quad + 4 * j) * 4;    // 4 cols, 64B-contig per row
                    float4 cc = *reinterpret_cast<const float4*>(C_s + row_l * CST + cb);
                    uint2 hh = *reinterpret_cast<const uint2*>(Ah + row * AST + cb);
                    uint2 ll = *reinterpret_cast<const uint2*>(Al + row * AST + cb);
                    __nv_bfloat162 h0 = *reinterpret_cast<__nv_bfloat162*>(&hh.x);
                    __nv_bfloat162 h1 = *reinterpret_cast<__nv_bfloat162*>(&hh.y);
                    __nv_bfloat162 l0 = *reinterpret_cast<__nv_bfloat162*>(&ll.x);
                    __nv_bfloat162 l1 = *reinterpret_cast<__nv_bfloat162*>(&ll.y);
                    float rr[4];
                    rr[0] = __bfloat162float(h0.x) + __bfloat162float(l0.x);
                    rr[1] = __bfloat162float(h0.y) + __bfloat162float(l0.y);
                    rr[2] = __bfloat162float(h1.x) + __bfloat162float(l1.x);
                    rr[3] = __bfloat162float(h1.y) + __bfloat162float(l1.y);
                    const float* cf = &cc.x;
                    #pragma unroll
                    for (int e = 0; e < 4; e++) {
                        float x = rr[e] + bo_s[cb + e] + mk * (cf[e] + cv_s[cb + e]);
                        s += x; s2 += x * x;
                        xv[j * 4 + e] = x;
                    }
                }
            }
            s  += __shfl_xor_sync(0xffffffffu, s, 1);
            s2 += __shfl_xor_sync(0xffffffffu, s2, 1);
            s  += __shfl_xor_sync(0xffffffffu, s, 2);
            s2 += __shfl_xor_sync(0xffffffffu, s2, 2);
            float mu = s * (1.f / 128.f);
            float rs = rsqrtf(s2 * (1.f / 128.f) - mu * mu + 1e-5f);
            if (gn < N) {
                float* op = outl + (size_t)gn * ND;
                #pragma unroll
                for (int j = 0; j < 8; j++) {
                    int cb = (quad + 4 * j) * 4;
                    float4 o;
                    o.x = (xv[j * 4 + 0] - mu) * rs * g_s[cb + 0] + b_s[cb + 0];
                    o.y = (xv[j * 4 + 1] - mu) * rs * g_s[cb + 1] + b_s[cb + 1];
                    o.z = (xv[j * 4 + 2] - mu) * rs * g_s[cb + 2] + b_s[cb + 2];
                    o.w = (xv[j * 4 + 3] - mu) * rs * g_s[cb + 3] + b_s[cb + 3];
                    *reinterpret_cast<float4*>(op + cb) = o;
                }
            }
        }
        __syncthreads();   // epilogue reads done before next half's C stores
    }
}

static const int SMEM_BYTES = (2 * NPB + ND) * AST * 2       // Ah, Al, Mx (bf16)
                            + (4 * ND + NPB) * (int)sizeof(float);  // params + mask

extern "C" void kernel_launch(void* const* d_in, const int* in_sizes, int n_in,
                              void* d_out, int out_size) {
    (void)n_in; (void)out_size;
    int NN[LVLS], NE[LVLS], noffA[LVLS];
    int cumN = 0;
    for (int i = 0; i < LVLS; i++) {
        NN[i] = in_sizes[i * 3] / ND;
        NE[i] = in_sizes[i * 3 + 2] / 2;
        noffA[i] = cumN;
        cumN += NN[i];
    }
    int ec4[LVLS]; int cumE4 = 0;
    for (int i = 0; i < LVLS; i++) { cumE4 += NE[i] / 4; ec4[i] = cumE4; }

    const float* Wv    = (const float*)d_in[16];
    const float* bv    = (const float*)d_in[17];
    const float* Wo    = (const float*)d_in[20];
    const float* bo    = (const float*)d_in[21];
    const float* gamma = (const float*)d_in[22];
    const float* beta  = (const float*)d_in[23];
    float* out = (float*)d_out;

    unsigned char* maskp = nullptr;
    __nv_bfloat16* Mhp = nullptr;
    __nv_bfloat16* Mlp = nullptr;
    float* cp = nullptr;
    cudaGetSymbolAddress((void**)&maskp, g_mask);
    cudaGetSymbolAddress((void**)&Mhp, g_Mh);
    cudaGetSymbolAddress((void**)&Mlp, g_Ml);
    cudaGetSymbolAddress((void**)&cp, g_c);

    cudaFuncSetAttribute(level_all_k, cudaFuncAttributeMaxDynamicSharedMemorySize, SMEM_BYTES);

    // 1) zero mask
    cudaMemsetAsync(maskp, 0, cumN);

    // 2) prep: M hi/lo bf16 + c + mask marking
    const int* t0 = (const int*)d_in[2]  + NE[0];
    const int* t1 = (const int*)d_in[5]  + NE[1];
    const int* t2 = (const int*)d_in[8]  + NE[2];
    const int* t3 = (const int*)d_in[11] + NE[3];
    int4 ecum4 = make_int4(ec4[0], ec4[1], ec4[2], ec4[3]);
    int4 noff = make_int4(noffA[0], noffA[1], noffA[2], noffA[3]);
    prep_all_k<<<LVLS * 64, PTPB>>>(Wv, Wo, bv, Mhp, Mlp, cp,
                                    t0, t1, t2, t3, ecum4, noff, maskp);

    // 3) wmma level kernel (2 CTAs/SM)
    int bs[LVLS], cumB = 0;
    for (int i = 0; i < LVLS; i++) { cumB += (NN[i] + NPB - 1) / NPB; bs[i] = cumB; }
    int4 bstart = make_int4(bs[0], bs[1], bs[2], bs[3]);
    int4 ncnt = make_int4(NN[0], NN[1], NN[2], NN[3]);
    level_all_k<<<cumB, LTPB, SMEM_BYTES>>>(
        (const float*)d_in[0], (const float*)d_in[3],
        (const float*)d_in[6], (const float*)d_in[9],
        maskp, Mhp, Mlp, cp, bo, gamma, beta, out, bstart, noff, ncnt);
}

// round 17
// speedup vs baseline: 1.4805x; 1.4087x over previous
#include <cuda_runtime.h>
#include <cuda_fp16.h>
#include <cstdint>
#include <mma.h>
using namespace nvcuda;

#define ND 128
#define HD 256
#define LVLS 4
#define PTPB 512
#define LTPB 256          // 8 warps
#define NPB 128
#define AST 136           // fp16 smem row stride (272 B)
#define CST 132           // fp32 C smem row stride
#define TOTAL_NODES 52400

__device__ __half g_Mh[LVLS][ND * ND];   // fp16 M = Wv@Wo, row-major [k][j]
__device__ float g_c[LVLS][ND];
__device__ unsigned char g_mask[TOTAL_NODES];

__device__ __forceinline__ int sel4(int4 v, int l) {
    return l == 0 ? v.x : l == 1 ? v.y : l == 2 ? v.z : v.w;
}

// Prep: M = Wv@Wo -> fp16 (row-major), c = bv@Wo, + mask scatter hidden
// under the Wo stream. Mask pre-zeroed by memset node.
__global__ __launch_bounds__(PTPB)
void prep_all_k(const float* __restrict__ Wv, const float* __restrict__ Wo,
                const float* __restrict__ bv, __half* __restrict__ Mh,
                float* __restrict__ cv,
                const int* __restrict__ t0, const int* __restrict__ t1,
                const int* __restrict__ t2, const int* __restrict__ t3,
                int4 ecum4, int4 noff, unsigned char* __restrict__ mask) {
    __shared__ float wv_s[2 * HD];
    __shared__ float bv_s[HD];
    __shared__ float part[9 * ND];

    const int tid = threadIdx.x;
    const int lvl = blockIdx.x >> 6, rg = blockIdx.x & 63;
    const int k0 = rg * 2;
    const float* Wvl = Wv + (size_t)lvl * ND * HD;
    const float* Wol = Wo + (size_t)lvl * HD * ND;
    const int j = tid & 127, th = tid >> 7;

    {
        int i = blockIdx.x * PTPB + tid;
        if (i < ecum4.w) {
            const int* t; int off, no;
            if (i < ecum4.x)      { t = t0; off = 0;       no = noff.x; }
            else if (i < ecum4.y) { t = t1; off = ecum4.x; no = noff.y; }
            else if (i < ecum4.z) { t = t2; off = ecum4.y; no = noff.z; }
            else                  { t = t3; off = ecum4.z; no = noff.w; }
            int4 v = reinterpret_cast<const int4*>(t)[i - off];
            unsigned char* mb = mask + no;
            mb[v.x] = 1; mb[v.y] = 1; mb[v.z] = 1; mb[v.w] = 1;
        }
    }

    if (tid < 2 * HD) wv_s[tid] = Wvl[k0 * HD + tid];
    if (tid < HD) bv_s[tid] = bv[lvl * HD + tid];
    __syncthreads();

    const int tBase = th * (HD / 4);
    float acc0 = 0.f, acc1 = 0.f, accc = 0.f;
    #pragma unroll
    for (int tt = 0; tt < HD / 4; tt += 16) {
        float wo[16];
        #pragma unroll
        for (int u = 0; u < 16; u++)
            wo[u] = Wol[(tBase + tt + u) * ND + j];
        #pragma unroll
        for (int u = 0; u < 16; u++) {
            int t = tBase + tt + u;
            acc0 += wv_s[t] * wo[u];
            acc1 += wv_s[HD + t] * wo[u];
            accc += bv_s[t] * wo[u];
        }
    }

    if (th > 0) {
        float* p = part + (th - 1) * 3 * ND;
        p[0 * ND + j] = acc0;
        p[1 * ND + j] = acc1;
        p[2 * ND + j] = accc;
    }
    __syncthreads();
    if (th == 0) {
        #pragma unroll
        for (int q = 0; q < 3; q++) {
            const float* p = part + q * 3 * ND;
            acc0 += p[0 * ND + j];
            acc1 += p[1 * ND + j];
            accc += p[2 * ND + j];
        }
        __half* Mhl = Mh + (size_t)lvl * ND * ND;
        Mhl[(k0 + 0) * ND + j] = __float2half_rn(acc0);
        Mhl[(k0 + 1) * ND + j] = __float2half_rn(acc1);
        if (rg == 0) cv[lvl * ND + j] = accc;
    }
}

// wmma level kernel, fp16 A-split, 2 passes (Ah*Mh + Al*Mh), 2 CTAs/SM.
// Epilogue: C overlays dead Mh region in two 64-row phases; mask/residual/LN.
__global__ __launch_bounds__(LTPB, 2)
void level_all_k(const float* __restrict__ n0i, const float* __restrict__ n1i,
                 const float* __restrict__ n2i, const float* __restrict__ n3i,
                 const unsigned char* __restrict__ mask,
                 const __half* __restrict__ Mhb,
                 const float* __restrict__ cvb, const float* __restrict__ bob,
                 const float* __restrict__ gb, const float* __restrict__ bb,
                 float* __restrict__ out, int4 bstart, int4 noff, int4 ncnt) {
    extern __shared__ char smraw[];
    __half* Ah = reinterpret_cast<__half*>(smraw);            // NPB*AST
    __half* Al = Ah + NPB * AST;
    __half* Mh = Al + NPB * AST;                              // ND*AST
    float* C_s  = reinterpret_cast<float*>(Mh);               // overlay after mainloop
    float* bo_s = reinterpret_cast<float*>(smraw + (2 * NPB + ND) * AST * 2);
    float* cv_s = bo_s + ND;
    float* g_s  = cv_s + ND;
    float* b_s  = g_s + ND;
    float* mk_s = b_s + ND;       // NPB

    const int tid = threadIdx.x;
    const int b = blockIdx.x;

    int lvl, b0;
    if (b < bstart.x)      { lvl = 0; b0 = 0; }
    else if (b < bstart.y) { lvl = 1; b0 = bstart.x; }
    else if (b < bstart.z) { lvl = 2; b0 = bstart.y; }
    else                   { lvl = 3; b0 = bstart.z; }

    const float* nodes = lvl == 0 ? n0i : lvl == 1 ? n1i : lvl == 2 ? n2i : n3i;
    const int N  = sel4(ncnt, lvl);
    const int nO = sel4(noff, lvl);
    float* outl = out + (size_t)nO * ND;
    const int nodeBase = (b - b0) * NPB;

    // params + mask
    if (tid < ND) {
        bo_s[tid] = bob[lvl * ND + tid];
        cv_s[tid] = cvb[lvl * ND + tid];
        g_s[tid]  = gb[lvl * ND + tid];
        b_s[tid]  = bb[lvl * ND + tid];
        int gn = nodeBase + tid;
        mk_s[tid] = (gn < N && mask[nO + gn]) ? 1.f : 0.f;
    }

    // Stage Mh (uint4 = 8 halves)
    {
        const uint4* mh4 = reinterpret_cast<const uint4*>(Mhb + (size_t)lvl * ND * ND);
        #pragma unroll
        for (int r = 0; r < 8; r++) {
            int idx = tid + r * LTPB;     // 0..2047 (128 rows x 16 chunks)
            int row = idx >> 4, c8 = idx & 15;
            *reinterpret_cast<uint4*>(Mh + row * AST + c8 * 8) = mh4[idx];
        }
    }

    // Stage A: fp32 coalesced -> fp16 hi/lo
    {
        const float4* nodes4 = reinterpret_cast<const float4*>(nodes);
        #pragma unroll
        for (int r = 0; r < 16; r++) {
            int idx = tid + r * LTPB;     // 0..4095 (128 rows x 32 float4)
            int node = idx >> 5, q = idx & 31;
            int gn = nodeBase + node;
            float4 v = (gn < N) ? nodes4[(size_t)gn * 32 + q]
                                : make_float4(0.f, 0.f, 0.f, 0.f);
            __half hx = __float2half_rn(v.x);
            __half hy = __float2half_rn(v.y);
            __half hz = __float2half_rn(v.z);
            __half hw = __float2half_rn(v.w);
            __half2 hA; hA.x = hx; hA.y = hy;
            __half2 hB; hB.x = hz; hB.y = hw;
            __half2 lA = __floats2half2_rn(v.x - __half2float(hx),
                                           v.y - __half2float(hy));
            __half2 lB = __floats2half2_rn(v.z - __half2float(hz),
                                           v.w - __half2float(hw));
            int off = node * AST + q * 4;
            *reinterpret_cast<__half2*>(Ah + off)     = hA;
            *reinterpret_cast<__half2*>(Ah + off + 2) = hB;
            *reinterpret_cast<__half2*>(Al + off)     = lA;
            *reinterpret_cast<__half2*>(Al + off + 2) = lB;
        }
    }
    __syncthreads();

    // Mainloop: 8 warps, warp tile 32 nodes x 64 cols, 2 passes.
    const int wid = tid >> 5;
    const int wr = wid >> 1, wc = wid & 1;
    wmma::fragment<wmma::accumulator, 16, 16, 16, float> acc[2][4];
    #pragma unroll
    for (int i = 0; i < 2; i++)
        #pragma unroll
        for (int j = 0; j < 4; j++) wmma::fill_fragment(acc[i][j], 0.f);

    #pragma unroll
    for (int p = 0; p < 2; p++) {
        const __half* Ap = p ? Al : Ah;
        #pragma unroll
        for (int k = 0; k < ND; k += 16) {
            wmma::fragment<wmma::matrix_a, 16, 16, 16, __half, wmma::row_major> af[2];
            wmma::load_matrix_sync(af[0], Ap + (wr * 32) * AST + k, AST);
            wmma::load_matrix_sync(af[1], Ap + (wr * 32 + 16) * AST + k, AST);
            #pragma unroll
            for (int j = 0; j < 4; j++) {
                wmma::fragment<wmma::matrix_b, 16, 16, 16, __half, wmma::row_major> bf;
                wmma::load_matrix_sync(bf, Mh + k * AST + wc * 64 + j * 16, AST);
                wmma::mma_sync(acc[0][j], af[0], bf, acc[0][j]);
                wmma::mma_sync(acc[1][j], af[1], bf, acc[1][j]);
            }
        }
    }
    __syncthreads();   // all Mh reads done before C_s overlays it

    // Two half-epilogues: rows [h*64, h*64+64)
    #pragma unroll
    for (int h = 0; h < 2; h++) {
        if ((wid >> 2) == h) {
            #pragma unroll
            for (int i = 0; i < 2; i++)
                #pragma unroll
                for (int j = 0; j < 4; j++)
                    wmma::store_matrix_sync(
                        C_s + (wr * 32 + i * 16 - h * 64) * CST + wc * 64 + j * 16,
                        acc[i][j], CST, wmma::mem_row_major);
        }
        __syncthreads();

        {
            const int row_l = tid >> 2, quad = tid & 3;
            const int row = h * 64 + row_l;
            const int gn = nodeBase + row;
            float s = 0.f, s2 = 0.f;
            float xv[32];
            if (gn < N) {
                float mk = mk_s[row];
                #pragma unroll
                for (int j = 0; j < 8; j++) {
                    int cb = (quad + 4 * j) * 4;
                    float4 cc = *reinterpret_cast<const float4*>(C_s + row_l * CST + cb);
                    __half2 h0 = *reinterpret_cast<const __half2*>(Ah + row * AST + cb);
                    __half2 h1 = *reinterpret_cast<const __half2*>(Ah + row * AST + cb + 2);
                    __half2 l0 = *reinterpret_cast<const __half2*>(Al + row * AST + cb);
                    __half2 l1 = *reinterpret_cast<const __half2*>(Al + row * AST + cb + 2);
                    float rr[4];
                    rr[0] = __half2float(h0.x) + __half2float(l0.x);
                    rr[1] = __half2float(h0.y) + __half2float(l0.y);
                    rr[2] = __half2float(h1.x) + __half2float(l1.x);
                    rr[3] = __half2float(h1.y) + __half2float(l1.y);
                    const float* cf = &cc.x;
                    #pragma unroll
                    for (int e = 0; e < 4; e++) {
                        float x = rr[e] + bo_s[cb + e] + mk * (cf[e] + cv_s[cb + e]);
                        s += x; s2 += x * x;
                        xv[j * 4 + e] = x;
                    }
                }
            }
            s  += __shfl_xor_sync(0xffffffffu, s, 1);
            s2 += __shfl_xor_sync(0xffffffffu, s2, 1);
            s  += __shfl_xor_sync(0xffffffffu, s, 2);
            s2 += __shfl_xor_sync(0xffffffffu, s2, 2);
            float mu = s * (1.f / 128.f);
            float rs = rsqrtf(s2 * (1.f / 128.f) - mu * mu + 1e-5f);
            if (gn < N) {
                float* op = outl + (size_t)gn * ND;
                #pragma unroll
                for (int j = 0; j < 8; j++) {
                    int cb = (quad + 4 * j) * 4;
                    float4 o;
                    o.x = (xv[j * 4 + 0] - mu) * rs * g_s[cb + 0] + b_s[cb + 0];
                    o.y = (xv[j * 4 + 1] - mu) * rs * g_s[cb + 1] + b_s[cb + 1];
                    o.z = (xv[j * 4 + 2] - mu) * rs * g_s[cb + 2] + b_s[cb + 2];
                    o.w = (xv[j * 4 + 3] - mu) * rs * g_s[cb + 3] + b_s[cb + 3];
                    *reinterpret_cast<float4*>(op + cb) = o;
                }
            }
        }
        __syncthreads();   // epilogue reads done before next half's C stores
    }
}

static const int SMEM_BYTES = (2 * NPB + ND) * AST * 2       // Ah, Al, Mh (fp16)
                            + (4 * ND + NPB) * (int)sizeof(float);  // params + mask

extern "C" void kernel_launch(void* const* d_in, const int* in_sizes, int n_in,
                              void* d_out, int out_size) {
    (void)n_in; (void)out_size;
    int NN[LVLS], NE[LVLS], noffA[LVLS];
    int cumN = 0;
    for (int i = 0; i < LVLS; i++) {
        NN[i] = in_sizes[i * 3] / ND;
        NE[i] = in_sizes[i * 3 + 2] / 2;
        noffA[i] = cumN;
        cumN += NN[i];
    }
    int ec4[LVLS]; int cumE4 = 0;
    for (int i = 0; i < LVLS; i++) { cumE4 += NE[i] / 4; ec4[i] = cumE4; }

    const float* Wv    = (const float*)d_in[16];
    const float* bv    = (const float*)d_in[17];
    const float* Wo    = (const float*)d_in[20];
    const float* bo    = (const float*)d_in[21];
    const float* gamma = (const float*)d_in[22];
    const float* beta  = (const float*)d_in[23];
    float* out = (float*)d_out;

    unsigned char* maskp = nullptr;
    __half* Mhp = nullptr;
    float* cp = nullptr;
    cudaGetSymbolAddress((void**)&maskp, g_mask);
    cudaGetSymbolAddress((void**)&Mhp, g_Mh);
    cudaGetSymbolAddress((void**)&cp, g_c);

    cudaFuncSetAttribute(level_all_k, cudaFuncAttributeMaxDynamicSharedMemorySize, SMEM_BYTES);

    // 1) zero mask
    cudaMemsetAsync(maskp, 0, cumN);

    // 2) prep: M fp16 + c + mask marking
    const int* t0 = (const int*)d_in[2]  + NE[0];
    const int* t1 = (const int*)d_in[5]  + NE[1];
    const int* t2 = (const int*)d_in[8]  + NE[2];
    const int* t3 = (const int*)d_in[11] + NE[3];
    int4 ecum4 = make_int4(ec4[0], ec4[1], ec4[2], ec4[3]);
    int4 noff = make_int4(noffA[0], noffA[1], noffA[2], noffA[3]);
    prep_all_k<<<LVLS * 64, PTPB>>>(Wv, Wo, bv, Mhp, cp,
                                    t0, t1, t2, t3, ecum4, noff, maskp);

    // 3) wmma level kernel (fp16 2-pass, 2 CTAs/SM)
    int bs[LVLS], cumB = 0;
    for (int i = 0; i < LVLS; i++) { cumB += (NN[i] + NPB - 1) / NPB; bs[i] = cumB; }
    int4 bstart = make_int4(bs[0], bs[1], bs[2], bs[3]);
    int4 ncnt = make_int4(NN[0], NN[1], NN[2], NN[3]);
    level_all_k<<<cumB, LTPB, SMEM_BYTES>>>(
        (const float*)d_in[0], (const float*)d_in[3],
        (const float*)d_in[6], (const float*)d_in[9],
        maskp, Mhp, cp, bo, gamma, beta, out, bstart, noff, ncnt);
}